// round 2
// baseline (speedup 1.0000x reference)
#include <cuda_runtime.h>

#define NTHR 512

// ---------------- shared memory layout (in floats) ----------------
#define WBT_SZ  (9*32*64)              // 18432 : wbT[a][i][o], o contiguous
#define WOT_SZ  (9*32*32)              //  9216 : woT[a][i][o]
#define XS_SZ   (32*68)                //  2176 : xs[i][k*4+t], row stride 68 (pad)
#define HS_SZ   (64*68)                //  4352 : hs[ch][k*4+t]
#define GS_SZ   (32*68)                //  2176 : gs[ch][k*4+t]
#define WBT_OFF 0
#define WOT_OFF (WBT_OFF + WBT_SZ)
#define XS_OFF  (WOT_OFF + WOT_SZ)
#define HS_OFF  (XS_OFF + XS_SZ)
#define GS_OFF  (HS_OFF + HS_SZ)
#define BB_OFF  (GS_OFF + GS_SZ)       // 64 floats
#define BO_OFF  (BB_OFF + 64)          // 32 floats
#define RW_OFF  (BO_OFF + 32)          // 4 floats
#define F_TOTAL (RW_OFF + 4)
#define I_TOTAL (256 + 256 + 16 + 16)  // gp terms, jc terms, counts
#define SMEM_BYTES ((F_TOTAL + I_TOTAL) * 4)

// ---------------- blade algebra constants ----------------
// blade order: 1,e0,e1,e2,e3,e01,e02,e03,e12,e13,e23,e012,e013,e023,e123,e0123
__constant__ int c_GRADE[16] = {0,1,1,1,1,2,2,2,2,2,2,3,3,3,3,4};
__constant__ int c_PART [16] = {-1,0,-1,-1,-1,2,3,4,-1,-1,-1,8,9,10,-1,14};
__constant__ int c_A2   [16] = {0,5,0,0,0,6,6,6,0,0,0,7,7,7,0,8};
__constant__ int c_EK[8]   = {1,5,6,7,11,12,13,15};   // e0-containing comps (64 MAC)
__constant__ int c_NK[8]   = {0,2,3,4,8,9,10,14};     // others (32 MAC)
__constant__ int c_KORD[16] = {1,5,6,7, 0,2,3,4, 11,12,13,15, 8,9,10,14}; // SMSP-balanced
__constant__ int c_MASK[16]  = {0,1,2,4,8,3,5,9,6,10,12,7,11,13,14,15};
__constant__ int c_IMASK[16] = {0,1,2,5,3,6,8,11,4,7,9,12,10,13,14,15};

__device__ __forceinline__ int inv_count(int A, int B) {
    int inv = 0;
    #pragma unroll
    for (int g = 0; g < 4; g++)
        if ((B >> g) & 1) inv += __popc(A >> (g + 1));
    return inv;
}

// equi_linear task: one (output channel o, component k), 4 tokens vectorized.
// wT: [a][i][co] with co contiguous (stride `co_stride` per i).
// xin rows: xin[i*68 + comp*4 + t].
__device__ __forceinline__ void equi_task(
    int k, int o, int co_stride, const float* __restrict__ wT,
    const float* __restrict__ xin, const float* __restrict__ bias,
    float* __restrict__ dst)
{
    float a0 = 0.f, a1 = 0.f, a2 = 0.f, a3 = 0.f;
    int g = c_GRADE[k];
    const float* w  = wT + (g * 32) * co_stride + o;
    const float* xc = xin + k * 4;
    #pragma unroll
    for (int i = 0; i < 32; i++) {
        float wv = w[i * co_stride];
        float4 xv = *(const float4*)(xc + i * 68);
        a0 = fmaf(wv, xv.x, a0); a1 = fmaf(wv, xv.y, a1);
        a2 = fmaf(wv, xv.z, a2); a3 = fmaf(wv, xv.w, a3);
    }
    int pk = c_PART[k];
    if (pk >= 0) {
        const float* w2 = wT + (c_A2[k] * 32) * co_stride + o;
        const float* x2 = xin + pk * 4;
        #pragma unroll
        for (int i = 0; i < 32; i++) {
            float wv = w2[i * co_stride];
            float4 xv = *(const float4*)(x2 + i * 68);
            a0 = fmaf(wv, xv.x, a0); a1 = fmaf(wv, xv.y, a1);
            a2 = fmaf(wv, xv.z, a2); a3 = fmaf(wv, xv.w, a3);
        }
    }
    if (k == 0) { float b = bias[o]; a0 += b; a1 += b; a2 += b; a3 += b; }
    *(float4*)(dst + o * 68 + k * 4) = make_float4(a0, a1, a2, a3);
}

__global__ __launch_bounds__(NTHR, 1)
void gatr_fused_kernel(
    const float* __restrict__ x, const float* __restrict__ ref,
    const float* __restrict__ w_bil, const float* __restrict__ b_bil,
    const float* __restrict__ w_out, const float* __restrict__ b_out,
    float* __restrict__ out, int ngroups)
{
    extern __shared__ float sm[];
    float* wbT = sm + WBT_OFF;
    float* woT = sm + WOT_OFF;
    float* xs  = sm + XS_OFF;   // also reused as output staging in P4/P5
    float* hs  = sm + HS_OFF;
    float* gs  = sm + GS_OFF;
    float* bb  = sm + BB_OFF;
    float* bo  = sm + BO_OFF;
    float* rw  = sm + RW_OFF;
    int* gp_t = (int*)(sm + F_TOTAL);
    int* jc_t = gp_t + 256;
    int* gp_n = jc_t + 256;
    int* jc_n = gp_n + 16;

    const int tid = threadIdx.x;

    // ---- stage weights transposed ----
    for (int e = tid; e < 64 * 32 * 9; e += NTHR) {
        int o = e / 288, r = e % 288, i = r / 9, a = r % 9;
        wbT[(a * 32 + i) * 64 + o] = w_bil[e];
    }
    for (int e = tid; e < 32 * 32 * 9; e += NTHR) {
        int o = e / 288, r = e % 288, i = r / 9, a = r % 9;
        woT[(a * 32 + i) * 32 + o] = w_out[e];
    }
    if (tid < 64) bb[tid] = b_bil[tid];
    if (tid < 32) bo[tid] = b_out[tid];

    // ---- build GP / JC term lists (deterministic, serial per table) ----
    if (tid == 0) {
        for (int k = 0; k < 16; k++) gp_n[k] = 0;
        for (int i = 0; i < 16; i++)
            for (int j = 0; j < 16; j++) {
                int A = c_MASK[i], B = c_MASK[j];
                if (A & B & 1) continue;                // e0*e0 = 0
                int s = inv_count(A, B) & 1;
                int k = c_IMASK[A ^ B];
                gp_t[k * 16 + gp_n[k]++] = i | (j << 5) | (s << 10);
            }
    }
    if (tid == 1) {
        int ds[16];
        for (int i = 0; i < 16; i++) {
            int A = c_MASK[i];
            ds[i] = (inv_count(A, 15 ^ A) & 1) ? -1 : 1;
        }
        for (int k = 0; k < 16; k++) jc_n[k] = 0;
        for (int i = 0; i < 16; i++)
            for (int j = 0; j < 16; j++) {
                int A = c_MASK[i], B = c_MASK[j];
                int da = 15 ^ A, db = 15 ^ B;
                if (da & db) continue;                  // wedge of duals vanishes
                int w = (inv_count(da, db) & 1) ? -1 : 1;
                int kk = c_IMASK[A & B];                // comp(da|db)
                int val = ds[i] * ds[j] * w * ds[kk];
                jc_t[kk * 16 + jc_n[kk]++] = i | (j << 5) | ((val < 0 ? 1 : 0) << 10);
            }
    }
    __syncthreads();

    for (int g = blockIdx.x; g < ngroups; g += gridDim.x) {
        // ---- P1: load 4 tokens of x into xs[i][k*4+t], and ref scalars ----
        {
            int t = tid >> 7, e = tid & 127;
            size_t tok = (size_t)g * 4 + t;
            float4 v = *(const float4*)(x + tok * 512 + (size_t)e * 4);
            float* b = xs + (e >> 2) * 68 + (e & 3) * 16 + t;
            b[0] = v.x; b[4] = v.y; b[8] = v.z; b[12] = v.w;
            if (tid < 4) rw[tid] = ref[((size_t)g * 4 + tid) * 16 + 15];
        }
        __syncthreads();

        // ---- P2: equi_linear #1 -> hs[64][16][4] (balanced E/N task split) ----
        {
            int q = tid >> 6, o = tid & 63;
            equi_task(c_EK[q], o, 64, wbT, xs, bb, hs);
            equi_task(c_NK[q], o, 64, wbT, xs, bb, hs);
        }
        __syncthreads();

        // ---- P3: geometric product + join -> gs[32][16][4] ----
        {
            int side = tid >> 8;          // 0 = GP, 1 = join
            int c    = (tid >> 4) & 15;
            int k    = tid & 15;
            const int* terms = (side ? jc_t : gp_t) + k * 16;
            int n            =  side ? jc_n[k]     : gp_n[k];
            const float* L = hs + (side * 32 + c) * 68;
            const float* R = hs + (side * 32 + 16 + c) * 68;
            float p0 = 0.f, p1 = 0.f, p2 = 0.f, p3 = 0.f;
            float q0 = 0.f, q1 = 0.f, q2 = 0.f, q3 = 0.f;
            for (int e = 0; e < n; e++) {
                int tm = terms[e];
                float4 av = *(const float4*)(L + (tm & 31) * 4);
                float4 bv = *(const float4*)(R + ((tm >> 5) & 31) * 4);
                if (tm & 1024) {
                    q0 = fmaf(av.x, bv.x, q0); q1 = fmaf(av.y, bv.y, q1);
                    q2 = fmaf(av.z, bv.z, q2); q3 = fmaf(av.w, bv.w, q3);
                } else {
                    p0 = fmaf(av.x, bv.x, p0); p1 = fmaf(av.y, bv.y, p1);
                    p2 = fmaf(av.z, bv.z, p2); p3 = fmaf(av.w, bv.w, p3);
                }
            }
            float r0 = p0 - q0, r1 = p1 - q1, r2 = p2 - q2, r3 = p3 - q3;
            if (side) { r0 *= rw[0]; r1 *= rw[1]; r2 *= rw[2]; r3 *= rw[3]; }
            *(float4*)(gs + (side * 16 + c) * 68 + k * 4) = make_float4(r0, r1, r2, r3);
        }
        __syncthreads();

        // ---- P4: equi_linear #2 -> staging in xs (reused) ----
        {
            int o = tid & 31;
            int k = c_KORD[tid >> 5];
            equi_task(k, o, 32, woT, gs, bo, xs);
        }
        __syncthreads();

        // ---- P5: coalesced store ----
        {
            int t = tid >> 7, e = tid & 127;
            size_t tok = (size_t)g * 4 + t;
            const float* b = xs + (e >> 2) * 68 + (e & 3) * 16 + t;
            float4 v = make_float4(b[0], b[4], b[8], b[12]);
            *(float4*)(out + tok * 512 + (size_t)e * 4) = v;
        }
        __syncthreads();
    }
}

extern "C" void kernel_launch(void* const* d_in, const int* in_sizes, int n_in,
                              void* d_out, int out_size)
{
    const float* x     = (const float*)d_in[0];
    const float* ref   = (const float*)d_in[1];
    const float* w_bil = (const float*)d_in[2];
    const float* b_bil = (const float*)d_in[3];
    const float* w_out = (const float*)d_in[4];
    const float* b_out = (const float*)d_in[5];
    float* out = (float*)d_out;

    int ntok    = in_sizes[0] / 512;   // 32 channels * 16 components
    int ngroups = ntok / 4;

    cudaFuncSetAttribute(gatr_fused_kernel,
                         cudaFuncAttributeMaxDynamicSharedMemorySize, SMEM_BYTES);
    gatr_fused_kernel<<<152, NTHR, SMEM_BYTES>>>(x, ref, w_bil, b_bil, w_out, b_out,
                                                 out, ngroups);
}

// round 3
// speedup vs baseline: 1.0019x; 1.0019x over previous
#include <cuda_runtime.h>

#define NTHR 512

// ---------------- shared memory layout (in floats) ----------------
#define WBT_SZ  (9*32*64)              // 18432 : wbT[a][i][o], o contiguous
#define WOT_SZ  (9*32*32)              //  9216 : woT[a][i][o]
#define XS_SZ   (32*68)                //  2176 : xs[i][k*4+t], row stride 68 (pad)
#define HS_SZ   (64*68)                //  4352 : hs[ch][k*4+t]
#define GS_SZ   (32*68)                //  2176 : gs[ch][k*4+t]
#define WBT_OFF 0
#define WOT_OFF (WBT_OFF + WBT_SZ)
#define XS_OFF  (WOT_OFF + WOT_SZ)
#define HS_OFF  (XS_OFF + XS_SZ)
#define GS_OFF  (HS_OFF + HS_SZ)
#define BB_OFF  (GS_OFF + GS_SZ)       // 64 floats
#define BO_OFF  (BB_OFF + 64)          // 32 floats
#define RW_OFF  (BO_OFF + 32)          // 4 floats
#define F_TOTAL (RW_OFF + 4)
#define I_TOTAL (256 + 256 + 16 + 16)  // gp terms, jc terms, counts
#define SMEM_BYTES ((F_TOTAL + I_TOTAL) * 4)

// ---------------- blade algebra constants ----------------
// blade order: 1,e0,e1,e2,e3,e01,e02,e03,e12,e13,e23,e012,e013,e023,e123,e0123
__constant__ int c_GRADE[16] = {0,1,1,1,1,2,2,2,2,2,2,3,3,3,3,4};
__constant__ int c_PART [16] = {-1,0,-1,-1,-1,2,3,4,-1,-1,-1,8,9,10,-1,14};
__constant__ int c_A2   [16] = {0,5,0,0,0,6,6,6,0,0,0,7,7,7,0,8};
__constant__ int c_EK[8]   = {1,5,6,7,11,12,13,15};   // e0-containing comps (64 MAC)
__constant__ int c_NK[8]   = {0,2,3,4,8,9,10,14};     // others (32 MAC)
__constant__ int c_KORD[16] = {1,5,6,7, 0,2,3,4, 11,12,13,15, 8,9,10,14}; // SMSP-balanced
__constant__ int c_MASK[16]  = {0,1,2,4,8,3,5,9,6,10,12,7,11,13,14,15};
__constant__ int c_IMASK[16] = {0,1,2,5,3,6,8,11,4,7,9,12,10,13,14,15};

__device__ __forceinline__ int inv_count(int A, int B) {
    int inv = 0;
    #pragma unroll
    for (int g = 0; g < 4; g++)
        if ((B >> g) & 1) inv += __popc(A >> (g + 1));
    return inv;
}

// equi_linear task: one (output channel o, component k), 4 tokens vectorized.
// wT: [a][i][co] with co contiguous (stride `co_stride` per i).
// xin rows: xin[i*68 + comp*4 + t].
__device__ __forceinline__ void equi_task(
    int k, int o, int co_stride, const float* __restrict__ wT,
    const float* __restrict__ xin, const float* __restrict__ bias,
    float* __restrict__ dst)
{
    float a0 = 0.f, a1 = 0.f, a2 = 0.f, a3 = 0.f;
    int g = c_GRADE[k];
    const float* w  = wT + (g * 32) * co_stride + o;
    const float* xc = xin + k * 4;
    #pragma unroll
    for (int i = 0; i < 32; i++) {
        float wv = w[i * co_stride];
        float4 xv = *(const float4*)(xc + i * 68);
        a0 = fmaf(wv, xv.x, a0); a1 = fmaf(wv, xv.y, a1);
        a2 = fmaf(wv, xv.z, a2); a3 = fmaf(wv, xv.w, a3);
    }
    int pk = c_PART[k];
    if (pk >= 0) {
        const float* w2 = wT + (c_A2[k] * 32) * co_stride + o;
        const float* x2 = xin + pk * 4;
        #pragma unroll
        for (int i = 0; i < 32; i++) {
            float wv = w2[i * co_stride];
            float4 xv = *(const float4*)(x2 + i * 68);
            a0 = fmaf(wv, xv.x, a0); a1 = fmaf(wv, xv.y, a1);
            a2 = fmaf(wv, xv.z, a2); a3 = fmaf(wv, xv.w, a3);
        }
    }
    if (k == 0) { float b = bias[o]; a0 += b; a1 += b; a2 += b; a3 += b; }
    *(float4*)(dst + o * 68 + k * 4) = make_float4(a0, a1, a2, a3);
}

__global__ __launch_bounds__(NTHR, 1)
void gatr_fused_kernel(
    const float* __restrict__ x, const float* __restrict__ ref,
    const float* __restrict__ w_bil, const float* __restrict__ b_bil,
    const float* __restrict__ w_out, const float* __restrict__ b_out,
    float* __restrict__ out, int ngroups)
{
    extern __shared__ float sm[];
    float* wbT = sm + WBT_OFF;
    float* woT = sm + WOT_OFF;
    float* xs  = sm + XS_OFF;   // also reused as output staging in P4/P5
    float* hs  = sm + HS_OFF;
    float* gs  = sm + GS_OFF;
    float* bb  = sm + BB_OFF;
    float* bo  = sm + BO_OFF;
    float* rw  = sm + RW_OFF;
    int* gp_t = (int*)(sm + F_TOTAL);
    int* jc_t = gp_t + 256;
    int* gp_n = jc_t + 256;
    int* jc_n = gp_n + 16;

    const int tid = threadIdx.x;

    // ---- stage weights transposed ----
    for (int e = tid; e < 64 * 32 * 9; e += NTHR) {
        int o = e / 288, r = e % 288, i = r / 9, a = r % 9;
        wbT[(a * 32 + i) * 64 + o] = w_bil[e];
    }
    for (int e = tid; e < 32 * 32 * 9; e += NTHR) {
        int o = e / 288, r = e % 288, i = r / 9, a = r % 9;
        woT[(a * 32 + i) * 32 + o] = w_out[e];
    }
    if (tid < 64) bb[tid] = b_bil[tid];
    if (tid < 32) bo[tid] = b_out[tid];

    // ---- build GP / JC term lists (deterministic, serial per table) ----
    if (tid == 0) {
        for (int k = 0; k < 16; k++) gp_n[k] = 0;
        for (int i = 0; i < 16; i++)
            for (int j = 0; j < 16; j++) {
                int A = c_MASK[i], B = c_MASK[j];
                if (A & B & 1) continue;                // e0*e0 = 0
                int s = inv_count(A, B) & 1;
                int k = c_IMASK[A ^ B];
                gp_t[k * 16 + gp_n[k]++] = i | (j << 5) | (s << 10);
            }
    }
    if (tid == 1) {
        int ds[16];
        for (int i = 0; i < 16; i++) {
            int A = c_MASK[i];
            ds[i] = (inv_count(A, 15 ^ A) & 1) ? -1 : 1;
        }
        for (int k = 0; k < 16; k++) jc_n[k] = 0;
        for (int i = 0; i < 16; i++)
            for (int j = 0; j < 16; j++) {
                int A = c_MASK[i], B = c_MASK[j];
                int da = 15 ^ A, db = 15 ^ B;
                if (da & db) continue;                  // wedge of duals vanishes
                int w = (inv_count(da, db) & 1) ? -1 : 1;
                int kk = c_IMASK[A & B];                // comp(da|db)
                int val = ds[i] * ds[j] * w * ds[kk];
                jc_t[kk * 16 + jc_n[kk]++] = i | (j << 5) | ((val < 0 ? 1 : 0) << 10);
            }
    }
    __syncthreads();

    for (int g = blockIdx.x; g < ngroups; g += gridDim.x) {
        // ---- P1: load 4 tokens of x into xs[i][k*4+t], and ref scalars ----
        {
            int t = tid >> 7, e = tid & 127;
            size_t tok = (size_t)g * 4 + t;
            float4 v = *(const float4*)(x + tok * 512 + (size_t)e * 4);
            float* b = xs + (e >> 2) * 68 + (e & 3) * 16 + t;
            b[0] = v.x; b[4] = v.y; b[8] = v.z; b[12] = v.w;
            if (tid < 4) rw[tid] = ref[((size_t)g * 4 + tid) * 16 + 15];
        }
        __syncthreads();

        // ---- P2: equi_linear #1 -> hs[64][16][4] (balanced E/N task split) ----
        {
            int q = tid >> 6, o = tid & 63;
            equi_task(c_EK[q], o, 64, wbT, xs, bb, hs);
            equi_task(c_NK[q], o, 64, wbT, xs, bb, hs);
        }
        __syncthreads();

        // ---- P3: geometric product + join -> gs[32][16][4] ----
        {
            int side = tid >> 8;          // 0 = GP, 1 = join
            int c    = (tid >> 4) & 15;
            int k    = tid & 15;
            const int* terms = (side ? jc_t : gp_t) + k * 16;
            int n            =  side ? jc_n[k]     : gp_n[k];
            const float* L = hs + (side * 32 + c) * 68;
            const float* R = hs + (side * 32 + 16 + c) * 68;
            float p0 = 0.f, p1 = 0.f, p2 = 0.f, p3 = 0.f;
            float q0 = 0.f, q1 = 0.f, q2 = 0.f, q3 = 0.f;
            for (int e = 0; e < n; e++) {
                int tm = terms[e];
                float4 av = *(const float4*)(L + (tm & 31) * 4);
                float4 bv = *(const float4*)(R + ((tm >> 5) & 31) * 4);
                if (tm & 1024) {
                    q0 = fmaf(av.x, bv.x, q0); q1 = fmaf(av.y, bv.y, q1);
                    q2 = fmaf(av.z, bv.z, q2); q3 = fmaf(av.w, bv.w, q3);
                } else {
                    p0 = fmaf(av.x, bv.x, p0); p1 = fmaf(av.y, bv.y, p1);
                    p2 = fmaf(av.z, bv.z, p2); p3 = fmaf(av.w, bv.w, p3);
                }
            }
            float r0 = p0 - q0, r1 = p1 - q1, r2 = p2 - q2, r3 = p3 - q3;
            if (side) { r0 *= rw[0]; r1 *= rw[1]; r2 *= rw[2]; r3 *= rw[3]; }
            *(float4*)(gs + (side * 16 + c) * 68 + k * 4) = make_float4(r0, r1, r2, r3);
        }
        __syncthreads();

        // ---- P4: equi_linear #2 -> staging in xs (reused) ----
        {
            int o = tid & 31;
            int k = c_KORD[tid >> 5];
            equi_task(k, o, 32, woT, gs, bo, xs);
        }
        __syncthreads();

        // ---- P5: coalesced store ----
        {
            int t = tid >> 7, e = tid & 127;
            size_t tok = (size_t)g * 4 + t;
            const float* b = xs + (e >> 2) * 68 + (e & 3) * 16 + t;
            float4 v = make_float4(b[0], b[4], b[8], b[12]);
            *(float4*)(out + tok * 512 + (size_t)e * 4) = v;
        }
        __syncthreads();
    }
}

extern "C" void kernel_launch(void* const* d_in, const int* in_sizes, int n_in,
                              void* d_out, int out_size)
{
    const float* x     = (const float*)d_in[0];
    const float* ref   = (const float*)d_in[1];
    const float* w_bil = (const float*)d_in[2];
    const float* b_bil = (const float*)d_in[3];
    const float* w_out = (const float*)d_in[4];
    const float* b_out = (const float*)d_in[5];
    float* out = (float*)d_out;

    int ntok    = in_sizes[0] / 512;   // 32 channels * 16 components
    int ngroups = ntok / 4;

    cudaFuncSetAttribute(gatr_fused_kernel,
                         cudaFuncAttributeMaxDynamicSharedMemorySize, SMEM_BYTES);
    gatr_fused_kernel<<<152, NTHR, SMEM_BYTES>>>(x, ref, w_bil, b_bil, w_out, b_out,
                                                 out, ngroups);
}